// round 2
// baseline (speedup 1.0000x reference)
#include <cuda_runtime.h>
#include <cuda_bf16.h>
#include <math.h>

// ---------------- problem constants ----------------
#define BB 4
#define TT 1024
#define DD 1024
#define HH 16
#define HS 64
#define EE 8
#define KK 2
#define DFF 4096
#define NTOK 4096            // B*T
#define CAPMAX 1024          // N*K/E

// ---------------- device scratch (no cudaMalloc allowed) ----------------
__device__ float g_h   [(size_t)NTOK * DD];
__device__ float g_q   [(size_t)NTOK * DD];
__device__ float g_k   [(size_t)NTOK * DD];
__device__ float g_v   [(size_t)NTOK * DD];
__device__ float g_attn[(size_t)NTOK * DD];
__device__ float g_x1  [(size_t)NTOK * DD];
__device__ float g_h2  [(size_t)NTOK * DD];
__device__ float g_mid [(size_t)EE * CAPMAX * DFF];   // 128 MB
__device__ float g_yout[(size_t)EE * CAPMAX * DD];    // 32 MB

__device__ int   g_idx    [NTOK * KK];
__device__ float g_gate   [NTOK * KK];
__device__ int   g_nsk    [NTOK];
__device__ int   g_n_ns;
__device__ int   g_cnt    [EE];
__device__ int   g_tok    [EE * CAPMAX];
__device__ int   g_slotmap[NTOK * KK];

// ---------------- init ----------------
__global__ void init_kernel() {
    int i = blockIdx.x * 256 + threadIdx.x;
    if (i < NTOK * KK) g_slotmap[i] = -1;
    if (i == 0) g_n_ns = 0;
}

// ---------------- layernorm (vectorized, one block per row) ----------------
__global__ __launch_bounds__(256) void ln_kernel(
    const float* __restrict__ x, const float* __restrict__ g,
    const float* __restrict__ b, float* __restrict__ o)
{
    int row = blockIdx.x;
    int tid = threadIdx.x;
    int lane = tid & 31, warp = tid >> 5;
    __shared__ float ws1[8], ws2[8];

    const float4 xv = *reinterpret_cast<const float4*>(x + (size_t)row * DD + tid * 4);
    float s  = xv.x + xv.y + xv.z + xv.w;
    float s2 = xv.x * xv.x + xv.y * xv.y + xv.z * xv.z + xv.w * xv.w;
#pragma unroll
    for (int off = 16; off; off >>= 1) {
        s  += __shfl_xor_sync(0xffffffffu, s,  off);
        s2 += __shfl_xor_sync(0xffffffffu, s2, off);
    }
    if (lane == 0) { ws1[warp] = s; ws2[warp] = s2; }
    __syncthreads();
    float ts = 0.f, ts2 = 0.f;
#pragma unroll
    for (int w = 0; w < 8; w++) { ts += ws1[w]; ts2 += ws2[w]; }
    float mean = ts * (1.f / DD);
    float var  = ts2 * (1.f / DD) - mean * mean;
    float inv  = rsqrtf(var + 1e-5f);

    const float4 gv = *reinterpret_cast<const float4*>(g + tid * 4);
    const float4 bv = *reinterpret_cast<const float4*>(b + tid * 4);
    float4 ov;
    ov.x = (xv.x - mean) * inv * gv.x + bv.x;
    ov.y = (xv.y - mean) * inv * gv.y + bv.y;
    ov.z = (xv.z - mean) * inv * gv.z + bv.z;
    ov.w = (xv.w - mean) * inv * gv.w + bv.w;
    *reinterpret_cast<float4*>(o + (size_t)row * DD + tid * 4) = ov;
}

// ---------------- generic tiled GEMM: 128x128x8, 8x8 micro ----------------
// C[row,col] = act( A[row,:] @ W[:,col] + bias[col] ) (+ resid[row,col])
// Per-z strides for expert batching; optional row gather; dynamic M via cntArr.
__global__ __launch_bounds__(256) void gemm_k(
    const float* __restrict__ A, size_t aStrideZ,
    const float* __restrict__ W, size_t wStrideZ,
    const float* __restrict__ bias, size_t bStrideZ,
    float* __restrict__ C, size_t cStrideZ,
    const float* __restrict__ resid,
    const int* __restrict__ rowidx, int ridxStrideZ,
    const int* __restrict__ cntArr,
    int Mfixed, int K, int Nc, int relu)
{
    int z = blockIdx.z;
    int M = cntArr ? cntArr[z] : Mfixed;
    int rowBase = blockIdx.y * 128;
    if (rowBase >= M) return;
    int colBase = blockIdx.x * 128;

    A += (size_t)z * aStrideZ;
    W += (size_t)z * wStrideZ;
    const float* bptr = bias ? bias + (size_t)z * bStrideZ : nullptr;
    C += (size_t)z * cStrideZ;
    const int* ridx = rowidx ? rowidx + (size_t)z * ridxStrideZ : nullptr;

    __shared__ float As[8][128];
    __shared__ float Bs[8][128];

    int tid = threadIdx.x;
    // A tile loads: 128 rows x 8 k ; 2 threads per row, float4 along k
    int arow_l = tid >> 1;
    int ak4    = (tid & 1) * 4;
    long aOff = -1;
    {
        int arow = rowBase + arow_l;
        if (arow < M) {
            int r = ridx ? ridx[arow] : arow;
            aOff = (long)r * K;
        }
    }
    // B tile loads: 8 k-rows x 128 cols ; 32 threads per k-row, float4 along n
    int bkrow = tid >> 5;
    int bcol  = (tid & 31) * 4;

    int ty = tid >> 4;   // 16 row groups of 8
    int tx = tid & 15;   // 16 col groups of 8

    float acc[8][8];
#pragma unroll
    for (int i = 0; i < 8; i++)
#pragma unroll
        for (int j = 0; j < 8; j++) acc[i][j] = 0.f;

    for (int k0 = 0; k0 < K; k0 += 8) {
        float4 av = make_float4(0.f, 0.f, 0.f, 0.f);
        if (aOff >= 0)
            av = *reinterpret_cast<const float4*>(A + aOff + k0 + ak4);
        float4 wv = *reinterpret_cast<const float4*>(W + (size_t)(k0 + bkrow) * Nc + colBase + bcol);

        As[ak4 + 0][arow_l] = av.x;
        As[ak4 + 1][arow_l] = av.y;
        As[ak4 + 2][arow_l] = av.z;
        As[ak4 + 3][arow_l] = av.w;
        *reinterpret_cast<float4*>(&Bs[bkrow][bcol]) = wv;
        __syncthreads();

#pragma unroll
        for (int kk = 0; kk < 8; kk++) {
            float4 a0 = *reinterpret_cast<float4*>(&As[kk][ty * 8]);
            float4 a1 = *reinterpret_cast<float4*>(&As[kk][ty * 8 + 4]);
            float4 b0 = *reinterpret_cast<float4*>(&Bs[kk][tx * 8]);
            float4 b1 = *reinterpret_cast<float4*>(&Bs[kk][tx * 8 + 4]);
            float aa[8] = {a0.x, a0.y, a0.z, a0.w, a1.x, a1.y, a1.z, a1.w};
            float bb[8] = {b0.x, b0.y, b0.z, b0.w, b1.x, b1.y, b1.z, b1.w};
#pragma unroll
            for (int i = 0; i < 8; i++)
#pragma unroll
                for (int j = 0; j < 8; j++) acc[i][j] += aa[i] * bb[j];
        }
        __syncthreads();
    }

#pragma unroll
    for (int i = 0; i < 8; i++) {
        int row = rowBase + ty * 8 + i;
        if (row >= M) continue;
        size_t rOff = (size_t)row * Nc;
#pragma unroll
        for (int j4 = 0; j4 < 2; j4++) {
            int col = colBase + tx * 8 + j4 * 4;
            float4 v;
            v.x = acc[i][j4 * 4 + 0];
            v.y = acc[i][j4 * 4 + 1];
            v.z = acc[i][j4 * 4 + 2];
            v.w = acc[i][j4 * 4 + 3];
            if (bptr) {
                float4 bvv = *reinterpret_cast<const float4*>(bptr + col);
                v.x += bvv.x; v.y += bvv.y; v.z += bvv.z; v.w += bvv.w;
            }
            if (relu) {
                v.x = fmaxf(v.x, 0.f); v.y = fmaxf(v.y, 0.f);
                v.z = fmaxf(v.z, 0.f); v.w = fmaxf(v.w, 0.f);
            }
            if (resid) {
                float4 rv = *reinterpret_cast<const float4*>(resid + rOff + col);
                v.x += rv.x; v.y += rv.y; v.z += rv.z; v.w += rv.w;
            }
            *reinterpret_cast<float4*>(C + rOff + col) = v;
        }
    }
}

// ---------------- flash-style causal attention ----------------
// 32-query x 32-key tiles, online softmax. Block: 256 threads.
// Thread micro-tiles: S -> 2 rows x 2 key-cols ; O -> 2 rows x 4 dims.
#define QB 32
__global__ __launch_bounds__(256) void attn_kernel(
    const float* __restrict__ q, const float* __restrict__ k,
    const float* __restrict__ v, float* __restrict__ out)
{
    int qb = blockIdx.x;             // query tile 0..31
    int bh = blockIdx.y;
    int b  = bh >> 4;
    int h  = bh & 15;
    int tid = threadIdx.x;

    __shared__ float Qs[QB][HS + 1];   // +1: conflict-free scalar column reads
    __shared__ float Ks[QB][HS + 1];
    __shared__ float Vs[QB][HS + 4];   // +4: aligned float4 rows
    __shared__ float Ps[QB][QB + 1];

    size_t base = (size_t)b * TT * DD + (size_t)h * HS;

    // load Q tile: 32 rows x 64 dims, 8 threads/row, 8 floats each
    {
        int r  = tid >> 3;
        int d0 = (tid & 7) * 8;
        const float* src = q + base + (size_t)(qb * QB + r) * DD + d0;
        float4 v0 = *reinterpret_cast<const float4*>(src);
        float4 v1 = *reinterpret_cast<const float4*>(src + 4);
        Qs[r][d0 + 0] = v0.x; Qs[r][d0 + 1] = v0.y; Qs[r][d0 + 2] = v0.z; Qs[r][d0 + 3] = v0.w;
        Qs[r][d0 + 4] = v1.x; Qs[r][d0 + 5] = v1.y; Qs[r][d0 + 6] = v1.z; Qs[r][d0 + 7] = v1.w;
    }

    int ty = tid >> 4;     // 0..15 -> rows ty*2, ty*2+1
    int tx = tid & 15;     // 0..15 -> key cols tx*2, tx*2+1 ; out dims tx*4..
    int r0 = ty * 2;
    int c0 = tx * 2;
    int d0 = tx * 4;

    float m[2]  = {-1e30f, -1e30f};
    float l[2]  = {0.f, 0.f};
    float accO[2][4] = {{0.f,0.f,0.f,0.f},{0.f,0.f,0.f,0.f}};

    for (int kt = 0; kt <= qb; kt++) {
        // load K/V tiles
        {
            int r  = tid >> 3;
            int dd = (tid & 7) * 8;
            const float* ksrc = k + base + (size_t)(kt * QB + r) * DD + dd;
            const float* vsrc = v + base + (size_t)(kt * QB + r) * DD + dd;
            float4 k0v = *reinterpret_cast<const float4*>(ksrc);
            float4 k1v = *reinterpret_cast<const float4*>(ksrc + 4);
            Ks[r][dd + 0] = k0v.x; Ks[r][dd + 1] = k0v.y; Ks[r][dd + 2] = k0v.z; Ks[r][dd + 3] = k0v.w;
            Ks[r][dd + 4] = k1v.x; Ks[r][dd + 5] = k1v.y; Ks[r][dd + 6] = k1v.z; Ks[r][dd + 7] = k1v.w;
            float4 v0v = *reinterpret_cast<const float4*>(vsrc);
            float4 v1v = *reinterpret_cast<const float4*>(vsrc + 4);
            *reinterpret_cast<float4*>(&Vs[r][dd])     = v0v;
            *reinterpret_cast<float4*>(&Vs[r][dd + 4]) = v1v;
        }
        __syncthreads();

        // S = Q K^T * scale  (2x2 per thread)
        float s00 = 0.f, s01 = 0.f, s10 = 0.f, s11 = 0.f;
#pragma unroll 16
        for (int dd = 0; dd < HS; dd++) {
            float q0 = Qs[r0][dd],     q1 = Qs[r0 + 1][dd];
            float kx = Ks[c0][dd],     ky = Ks[c0 + 1][dd];
            s00 += q0 * kx; s01 += q0 * ky;
            s10 += q1 * kx; s11 += q1 * ky;
        }
        const float SCALE = 0.03125f;  // D^{-1/2} = 1/32
        s00 *= SCALE; s01 *= SCALE; s10 *= SCALE; s11 *= SCALE;

        if (kt == qb) {                // causal mask on the diagonal tile
            if (c0 + 0 > r0 + 0) s00 = -1e30f;
            if (c0 + 1 > r0 + 0) s01 = -1e30f;
            if (c0 + 0 > r0 + 1) s10 = -1e30f;
            if (c0 + 1 > r0 + 1) s11 = -1e30f;
        }

        // per-row online softmax update (reduce across the 16 tx lanes)
        float rm0 = fmaxf(s00, s01);
        float rm1 = fmaxf(s10, s11);
#pragma unroll
        for (int off = 8; off; off >>= 1) {
            rm0 = fmaxf(rm0, __shfl_xor_sync(0xffffffffu, rm0, off));
            rm1 = fmaxf(rm1, __shfl_xor_sync(0xffffffffu, rm1, off));
        }
        float mn0 = fmaxf(m[0], rm0);
        float mn1 = fmaxf(m[1], rm1);
        float p00 = expf(s00 - mn0), p01 = expf(s01 - mn0);
        float p10 = expf(s10 - mn1), p11 = expf(s11 - mn1);
        float ps0 = p00 + p01, ps1 = p10 + p11;
#pragma unroll
        for (int off = 8; off; off >>= 1) {
            ps0 += __shfl_xor_sync(0xffffffffu, ps0, off);
            ps1 += __shfl_xor_sync(0xffffffffu, ps1, off);
        }
        float sc0 = expf(m[0] - mn0);
        float sc1 = expf(m[1] - mn1);
        l[0] = l[0] * sc0 + ps0;
        l[1] = l[1] * sc1 + ps1;
        m[0] = mn0; m[1] = mn1;
#pragma unroll
        for (int j = 0; j < 4; j++) { accO[0][j] *= sc0; accO[1][j] *= sc1; }

        Ps[r0][c0]         = p00;
        Ps[r0][c0 + 1]     = p01;
        Ps[r0 + 1][c0]     = p10;
        Ps[r0 + 1][c0 + 1] = p11;
        __syncthreads();

        // O += P V  (2 rows x 4 dims per thread)
#pragma unroll 8
        for (int kk = 0; kk < QB; kk++) {
            float pa = Ps[r0][kk];
            float pb = Ps[r0 + 1][kk];
            float4 vv = *reinterpret_cast<float4*>(&Vs[kk][d0]);
            accO[0][0] += pa * vv.x; accO[0][1] += pa * vv.y;
            accO[0][2] += pa * vv.z; accO[0][3] += pa * vv.w;
            accO[1][0] += pb * vv.x; accO[1][1] += pb * vv.y;
            accO[1][2] += pb * vv.z; accO[1][3] += pb * vv.w;
        }
        __syncthreads();
    }

    // final normalize + write
#pragma unroll
    for (int i = 0; i < 2; i++) {
        float invl = 1.f / l[i];
        float4 ov;
        ov.x = accO[i][0] * invl; ov.y = accO[i][1] * invl;
        ov.z = accO[i][2] * invl; ov.w = accO[i][3] * invl;
        *reinterpret_cast<float4*>(out + base + (size_t)(qb * QB + r0 + i) * DD + d0) = ov;
    }
}

// ---------------- router: logits, noisy top-2, gates, skip ----------------
__global__ __launch_bounds__(256) void router_kernel(
    const float* __restrict__ h2,
    const float* __restrict__ wr, const float* __restrict__ br,
    const float* __restrict__ wn, const float* __restrict__ bn,
    const float* __restrict__ ws, const float* __restrict__ bs,
    const float* __restrict__ noise)
{
    int t = blockIdx.x;
    int tid = threadIdx.x;
    int lane = tid & 31, warp = tid >> 5;
    __shared__ float sred[8][17];
    __shared__ float outv[17];

    const float* hr = h2 + (size_t)t * DD;
    float r[EE], nz[EE];
#pragma unroll
    for (int e = 0; e < EE; e++) { r[e] = 0.f; nz[e] = 0.f; }
    float sk = 0.f;
    for (int d = tid; d < DD; d += 256) {
        float hv = hr[d];
#pragma unroll
        for (int e = 0; e < EE; e++) {
            r[e]  += hv * wr[d * EE + e];
            nz[e] += hv * wn[d * EE + e];
        }
        sk += hv * ws[d];
    }
#pragma unroll
    for (int o = 0; o < 17; o++) {
        float val = (o < 8) ? r[o] : ((o < 16) ? nz[o - 8] : sk);
#pragma unroll
        for (int off = 16; off; off >>= 1)
            val += __shfl_xor_sync(0xffffffffu, val, off);
        if (lane == 0) sred[warp][o] = val;
    }
    __syncthreads();
    if (tid < 17) {
        float s = 0.f;
#pragma unroll
        for (int w = 0; w < 8; w++) s += sred[w][tid];
        outv[tid] = s;
    }
    __syncthreads();
    if (tid == 0) {
        float noisy[EE];
#pragma unroll
        for (int e = 0; e < EE; e++) {
            float logit = outv[e] + br[e];
            float nlin  = outv[8 + e] + bn[e];
            float sp = (nlin > 20.f) ? nlin : log1pf(expf(nlin));   // softplus
            noisy[e] = logit + noise[(size_t)t * EE + e] * sp;
        }
        int i1 = 0; float v1 = noisy[0];
#pragma unroll
        for (int e = 1; e < EE; e++) if (noisy[e] > v1) { v1 = noisy[e]; i1 = e; }
        int i2 = -1; float v2 = -1e30f;
#pragma unroll
        for (int e = 0; e < EE; e++) if (e != i1 && noisy[e] > v2) { v2 = noisy[e]; i2 = e; }
        float e2  = expf(v2 - v1);
        float inv = 1.f / (1.f + e2);
        g_idx [t * KK + 0] = i1;
        g_idx [t * KK + 1] = i2;
        g_gate[t * KK + 0] = inv;
        g_gate[t * KK + 1] = e2 * inv;
        float s = outv[16] + bs[0];
        int ns = (s > 0.f) ? 0 : 1;              // skip <=> sigmoid(s)>0.5 <=> s>0
        g_nsk[t] = ns;
        if (ns) atomicAdd(&g_n_ns, 1);
    }
}

// ---------------- per-expert dispatch (token-order scan, capacity) ----------------
__global__ __launch_bounds__(256) void dispatch_kernel()
{
    int e = blockIdx.x;
    int tid = threadIdx.x;
    __shared__ int sb[256];
    int cap = (g_n_ns * KK) / EE;
    int running = 0;
    for (int base = 0; base < NTOK; base += 256) {
        int t = base + tid;
        int f0 = g_idx[t * KK + 0];
        int f1 = g_idx[t * KK + 1];
        int mk = (g_nsk[t] && (f0 == e || f1 == e)) ? 1 : 0;
        sb[tid] = mk; __syncthreads();
        for (int off = 1; off < 256; off <<= 1) {
            int vv = (tid >= off) ? sb[tid - off] : 0;
            __syncthreads();
            sb[tid] += vv;
            __syncthreads();
        }
        if (mk) {
            int slot = running + sb[tid] - 1;
            if (slot < cap) {
                g_tok[e * CAPMAX + slot] = t;
                int j = (f0 == e) ? 0 : 1;
                g_slotmap[t * KK + j] = slot;
            }
        }
        int tot = sb[255];
        __syncthreads();
        running += tot;
    }
    if (tid == 0) g_cnt[e] = (running < cap) ? running : cap;
}

// ---------------- combine: out = x1 + (nsk ? expert mix : h2) ----------------
__global__ __launch_bounds__(256) void combine_kernel(
    const float* __restrict__ x1, const float* __restrict__ h2,
    const float* __restrict__ yout, float* __restrict__ out)
{
    int t = blockIdx.x;
    int tid = threadIdx.x;
    int d = tid * 4;
    int ns = g_nsk[t];
    float4 moe;
    if (ns) {
        int e0 = g_idx[t * KK + 0], e1 = g_idx[t * KK + 1];
        int s0 = g_slotmap[t * KK + 0], s1 = g_slotmap[t * KK + 1];
        float ga = g_gate[t * KK + 0], gb = g_gate[t * KK + 1];
        moe = make_float4(0.f, 0.f, 0.f, 0.f);
        if (s0 >= 0) {
            float4 y = *reinterpret_cast<const float4*>(yout + ((size_t)e0 * CAPMAX + s0) * DD + d);
            moe.x += ga * y.x; moe.y += ga * y.y; moe.z += ga * y.z; moe.w += ga * y.w;
        }
        if (s1 >= 0) {
            float4 y = *reinterpret_cast<const float4*>(yout + ((size_t)e1 * CAPMAX + s1) * DD + d);
            moe.x += gb * y.x; moe.y += gb * y.y; moe.z += gb * y.z; moe.w += gb * y.w;
        }
    } else {
        moe = *reinterpret_cast<const float4*>(h2 + (size_t)t * DD + d);
    }
    float4 xv = *reinterpret_cast<const float4*>(x1 + (size_t)t * DD + d);
    float4 ov;
    ov.x = xv.x + moe.x; ov.y = xv.y + moe.y;
    ov.z = xv.z + moe.z; ov.w = xv.w + moe.w;
    *reinterpret_cast<float4*>(out + (size_t)t * DD + d) = ov;
}

// ---------------- launch ----------------
extern "C" void kernel_launch(void* const* d_in, const int* in_sizes, int n_in,
                              void* d_out, int out_size)
{
    const float* x        = (const float*)d_in[0];
    const float* noise    = (const float*)d_in[1];
    const float* ln1_g    = (const float*)d_in[2];
    const float* ln1_b    = (const float*)d_in[3];
    const float* wq       = (const float*)d_in[4];
    const float* wk       = (const float*)d_in[5];
    const float* wv       = (const float*)d_in[6];
    const float* w_proj   = (const float*)d_in[7];
    const float* b_proj   = (const float*)d_in[8];
    const float* ln2_g    = (const float*)d_in[9];
    const float* ln2_b    = (const float*)d_in[10];
    const float* w_router = (const float*)d_in[11];
    const float* b_router = (const float*)d_in[12];
    const float* w_noise  = (const float*)d_in[13];
    const float* b_noise  = (const float*)d_in[14];
    const float* w_skip   = (const float*)d_in[15];
    const float* b_skip   = (const float*)d_in[16];
    const float* ew1      = (const float*)d_in[17];
    const float* eb1      = (const float*)d_in[18];
    const float* ew2      = (const float*)d_in[19];
    const float* eb2      = (const float*)d_in[20];
    float* out = (float*)d_out;

    float *p_h, *p_q, *p_k, *p_v, *p_attn, *p_x1, *p_h2, *p_mid, *p_yout;
    int *p_tok, *p_cnt;
    cudaGetSymbolAddress((void**)&p_h,    g_h);
    cudaGetSymbolAddress((void**)&p_q,    g_q);
    cudaGetSymbolAddress((void**)&p_k,    g_k);
    cudaGetSymbolAddress((void**)&p_v,    g_v);
    cudaGetSymbolAddress((void**)&p_attn, g_attn);
    cudaGetSymbolAddress((void**)&p_x1,   g_x1);
    cudaGetSymbolAddress((void**)&p_h2,   g_h2);
    cudaGetSymbolAddress((void**)&p_mid,  g_mid);
    cudaGetSymbolAddress((void**)&p_yout, g_yout);
    cudaGetSymbolAddress((void**)&p_tok,  g_tok);
    cudaGetSymbolAddress((void**)&p_cnt,  g_cnt);

    // 1. reset per-launch state
    init_kernel<<<32, 256>>>();

    // 2. LN1
    ln_kernel<<<NTOK, 256>>>(x, ln1_g, ln1_b, p_h);

    // 3. QKV projections (4096x1024x1024 each)
    gemm_k<<<dim3(8, 32, 1), 256>>>(p_h, 0, wq, 0, nullptr, 0, p_q, 0,
                                    nullptr, nullptr, 0, nullptr, NTOK, DD, DD, 0);
    gemm_k<<<dim3(8, 32, 1), 256>>>(p_h, 0, wk, 0, nullptr, 0, p_k, 0,
                                    nullptr, nullptr, 0, nullptr, NTOK, DD, DD, 0);
    gemm_k<<<dim3(8, 32, 1), 256>>>(p_h, 0, wv, 0, nullptr, 0, p_v, 0,
                                    nullptr, nullptr, 0, nullptr, NTOK, DD, DD, 0);

    // 4. flash-style causal attention
    attn_kernel<<<dim3(TT / QB, BB * HH), 256>>>(p_q, p_k, p_v, p_attn);

    // 5. output projection + bias + residual -> x1
    gemm_k<<<dim3(8, 32, 1), 256>>>(p_attn, 0, w_proj, 0, b_proj, 0, p_x1, 0,
                                    x, nullptr, 0, nullptr, NTOK, DD, DD, 0);

    // 6. LN2
    ln_kernel<<<NTOK, 256>>>(p_x1, ln2_g, ln2_b, p_h2);

    // 7. router
    router_kernel<<<NTOK, 256>>>(p_h2, w_router, b_router, w_noise, b_noise,
                                 w_skip, b_skip, noise);

    // 8. capacity-limited per-expert dispatch
    dispatch_kernel<<<EE, 256>>>();

    // 9. expert FFN layer 1 (gathered rows, +bias, ReLU): M<=1024, N=4096, K=1024
    gemm_k<<<dim3(32, 8, EE), 256>>>(p_h2, 0,
                                     ew1, (size_t)DD * DFF,
                                     eb1, (size_t)DFF,
                                     p_mid, (size_t)CAPMAX * DFF,
                                     nullptr, p_tok, CAPMAX, p_cnt,
                                     0, DD, DFF, 1);

    // 10. expert FFN layer 2 (+bias): M<=1024, N=1024, K=4096
    gemm_k<<<dim3(8, 8, EE), 256>>>(p_mid, (size_t)CAPMAX * DFF,
                                    ew2, (size_t)DFF * DD,
                                    eb2, (size_t)DD,
                                    p_yout, (size_t)CAPMAX * DD,
                                    nullptr, nullptr, 0, p_cnt,
                                    0, DFF, DD, 0);

    // 11. combine + final residual -> out
    combine_kernel<<<NTOK, 256>>>(p_x1, p_h2, p_yout, out);
}

// round 3
// speedup vs baseline: 1.0064x; 1.0064x over previous
#include <cuda_runtime.h>
#include <cuda_bf16.h>
#include <math.h>

// ---------------- problem constants ----------------
#define BB 4
#define TT 1024
#define DD 1024
#define HH 16
#define HS 64
#define EE 8
#define KK 2
#define DFF 4096
#define NTOK 4096            // B*T
#define CAPMAX 1024          // N*K/E

// ---------------- device scratch (no cudaMalloc allowed) ----------------
__device__ float g_h   [(size_t)NTOK * DD];
__device__ float g_q   [(size_t)NTOK * DD];
__device__ float g_k   [(size_t)NTOK * DD];
__device__ float g_v   [(size_t)NTOK * DD];
__device__ float g_attn[(size_t)NTOK * DD];
__device__ float g_x1  [(size_t)NTOK * DD];
__device__ float g_h2  [(size_t)NTOK * DD];
__device__ float g_mid [(size_t)EE * CAPMAX * DFF];   // 128 MB
__device__ float g_yout[(size_t)EE * CAPMAX * DD];    // 32 MB

__device__ int   g_idx    [NTOK * KK];
__device__ float g_gate   [NTOK * KK];
__device__ int   g_nsk    [NTOK];
__device__ int   g_n_ns;
__device__ int   g_cnt    [EE];
__device__ int   g_tok    [EE * CAPMAX];
__device__ int   g_slotmap[NTOK * KK];

// ---------------- init ----------------
__global__ void init_kernel() {
    int i = blockIdx.x * 256 + threadIdx.x;
    if (i < NTOK * KK) g_slotmap[i] = -1;
    if (i == 0) g_n_ns = 0;
}

// ---------------- layernorm (vectorized, one block per row) ----------------
__global__ __launch_bounds__(256) void ln_kernel(
    const float* __restrict__ x, const float* __restrict__ g,
    const float* __restrict__ b, float* __restrict__ o)
{
    int row = blockIdx.x;
    int tid = threadIdx.x;
    int lane = tid & 31, warp = tid >> 5;
    __shared__ float ws1[8], ws2[8];

    const float4 xv = *reinterpret_cast<const float4*>(x + (size_t)row * DD + tid * 4);
    float s  = xv.x + xv.y + xv.z + xv.w;
    float s2 = xv.x * xv.x + xv.y * xv.y + xv.z * xv.z + xv.w * xv.w;
#pragma unroll
    for (int off = 16; off; off >>= 1) {
        s  += __shfl_xor_sync(0xffffffffu, s,  off);
        s2 += __shfl_xor_sync(0xffffffffu, s2, off);
    }
    if (lane == 0) { ws1[warp] = s; ws2[warp] = s2; }
    __syncthreads();
    float ts = 0.f, ts2 = 0.f;
#pragma unroll
    for (int w = 0; w < 8; w++) { ts += ws1[w]; ts2 += ws2[w]; }
    float mean = ts * (1.f / DD);
    float var  = ts2 * (1.f / DD) - mean * mean;
    float inv  = rsqrtf(var + 1e-5f);

    const float4 gv = *reinterpret_cast<const float4*>(g + tid * 4);
    const float4 bv = *reinterpret_cast<const float4*>(b + tid * 4);
    float4 ov;
    ov.x = (xv.x - mean) * inv * gv.x + bv.x;
    ov.y = (xv.y - mean) * inv * gv.y + bv.y;
    ov.z = (xv.z - mean) * inv * gv.z + bv.z;
    ov.w = (xv.w - mean) * inv * gv.w + bv.w;
    *reinterpret_cast<float4*>(o + (size_t)row * DD + tid * 4) = ov;
}

// ---------------- generic tiled GEMM: 128x128x8, 8x8 micro ----------------
// C[row,col] = act( A[row,:] @ W[:,col] + bias[col] ) (+ resid[row,col])
// Per-z strides for expert batching; optional row gather; dynamic M via cntArr.
__global__ __launch_bounds__(256) void gemm_k(
    const float* __restrict__ A, size_t aStrideZ,
    const float* __restrict__ W, size_t wStrideZ,
    const float* __restrict__ bias, size_t bStrideZ,
    float* __restrict__ C, size_t cStrideZ,
    const float* __restrict__ resid,
    const int* __restrict__ rowidx, int ridxStrideZ,
    const int* __restrict__ cntArr,
    int Mfixed, int K, int Nc, int relu)
{
    int z = blockIdx.z;
    int M = cntArr ? cntArr[z] : Mfixed;
    int rowBase = blockIdx.y * 128;
    if (rowBase >= M) return;
    int colBase = blockIdx.x * 128;

    A += (size_t)z * aStrideZ;
    W += (size_t)z * wStrideZ;
    const float* bptr = bias ? bias + (size_t)z * bStrideZ : nullptr;
    C += (size_t)z * cStrideZ;
    const int* ridx = rowidx ? rowidx + (size_t)z * ridxStrideZ : nullptr;

    __shared__ float As[8][128];
    __shared__ float Bs[8][128];

    int tid = threadIdx.x;
    // A tile loads: 128 rows x 8 k ; 2 threads per row, float4 along k
    int arow_l = tid >> 1;
    int ak4    = (tid & 1) * 4;
    long aOff = -1;
    {
        int arow = rowBase + arow_l;
        if (arow < M) {
            int r = ridx ? ridx[arow] : arow;
            aOff = (long)r * K;
        }
    }
    // B tile loads: 8 k-rows x 128 cols ; 32 threads per k-row, float4 along n
    int bkrow = tid >> 5;
    int bcol  = (tid & 31) * 4;

    int ty = tid >> 4;   // 16 row groups of 8
    int tx = tid & 15;   // 16 col groups of 8

    float acc[8][8];
#pragma unroll
    for (int i = 0; i < 8; i++)
#pragma unroll
        for (int j = 0; j < 8; j++) acc[i][j] = 0.f;

    for (int k0 = 0; k0 < K; k0 += 8) {
        float4 av = make_float4(0.f, 0.f, 0.f, 0.f);
        if (aOff >= 0)
            av = *reinterpret_cast<const float4*>(A + aOff + k0 + ak4);
        float4 wv = *reinterpret_cast<const float4*>(W + (size_t)(k0 + bkrow) * Nc + colBase + bcol);

        As[ak4 + 0][arow_l] = av.x;
        As[ak4 + 1][arow_l] = av.y;
        As[ak4 + 2][arow_l] = av.z;
        As[ak4 + 3][arow_l] = av.w;
        *reinterpret_cast<float4*>(&Bs[bkrow][bcol]) = wv;
        __syncthreads();

#pragma unroll
        for (int kk = 0; kk < 8; kk++) {
            float4 a0 = *reinterpret_cast<float4*>(&As[kk][ty * 8]);
            float4 a1 = *reinterpret_cast<float4*>(&As[kk][ty * 8 + 4]);
            float4 b0 = *reinterpret_cast<float4*>(&Bs[kk][tx * 8]);
            float4 b1 = *reinterpret_cast<float4*>(&Bs[kk][tx * 8 + 4]);
            float aa[8] = {a0.x, a0.y, a0.z, a0.w, a1.x, a1.y, a1.z, a1.w};
            float bb[8] = {b0.x, b0.y, b0.z, b0.w, b1.x, b1.y, b1.z, b1.w};
#pragma unroll
            for (int i = 0; i < 8; i++)
#pragma unroll
                for (int j = 0; j < 8; j++) acc[i][j] += aa[i] * bb[j];
        }
        __syncthreads();
    }

#pragma unroll
    for (int i = 0; i < 8; i++) {
        int row = rowBase + ty * 8 + i;
        if (row >= M) continue;
        size_t rOff = (size_t)row * Nc;
#pragma unroll
        for (int j4 = 0; j4 < 2; j4++) {
            int col = colBase + tx * 8 + j4 * 4;
            float4 v;
            v.x = acc[i][j4 * 4 + 0];
            v.y = acc[i][j4 * 4 + 1];
            v.z = acc[i][j4 * 4 + 2];
            v.w = acc[i][j4 * 4 + 3];
            if (bptr) {
                float4 bvv = *reinterpret_cast<const float4*>(bptr + col);
                v.x += bvv.x; v.y += bvv.y; v.z += bvv.z; v.w += bvv.w;
            }
            if (relu) {
                v.x = fmaxf(v.x, 0.f); v.y = fmaxf(v.y, 0.f);
                v.z = fmaxf(v.z, 0.f); v.w = fmaxf(v.w, 0.f);
            }
            if (resid) {
                float4 rv = *reinterpret_cast<const float4*>(resid + rOff + col);
                v.x += rv.x; v.y += rv.y; v.z += rv.z; v.w += rv.w;
            }
            *reinterpret_cast<float4*>(C + rOff + col) = v;
        }
    }
}

// ---------------- flash-style causal attention ----------------
// 32-query x 32-key tiles, online softmax. Block: 256 threads.
// Thread micro-tiles: S -> 2 rows x 2 key-cols ; O -> 2 rows x 4 dims.
#define QB 32
__global__ __launch_bounds__(256) void attn_kernel(
    const float* __restrict__ q, const float* __restrict__ k,
    const float* __restrict__ v, float* __restrict__ out)
{
    int qb = blockIdx.x;             // query tile 0..31
    int bh = blockIdx.y;
    int b  = bh >> 4;
    int h  = bh & 15;
    int tid = threadIdx.x;

    __shared__ float Qs[QB][HS + 1];   // +1: conflict-free scalar column reads
    __shared__ float Ks[QB][HS + 1];
    __shared__ float Vs[QB][HS + 4];   // +4: aligned float4 rows
    __shared__ float Ps[QB][QB + 1];

    size_t base = (size_t)b * TT * DD + (size_t)h * HS;

    // load Q tile: 32 rows x 64 dims, 8 threads/row, 8 floats each
    {
        int r  = tid >> 3;
        int d0 = (tid & 7) * 8;
        const float* src = q + base + (size_t)(qb * QB + r) * DD + d0;
        float4 v0 = *reinterpret_cast<const float4*>(src);
        float4 v1 = *reinterpret_cast<const float4*>(src + 4);
        Qs[r][d0 + 0] = v0.x; Qs[r][d0 + 1] = v0.y; Qs[r][d0 + 2] = v0.z; Qs[r][d0 + 3] = v0.w;
        Qs[r][d0 + 4] = v1.x; Qs[r][d0 + 5] = v1.y; Qs[r][d0 + 6] = v1.z; Qs[r][d0 + 7] = v1.w;
    }

    int ty = tid >> 4;     // 0..15 -> rows ty*2, ty*2+1
    int tx = tid & 15;     // 0..15 -> key cols tx*2, tx*2+1 ; out dims tx*4..
    int r0 = ty * 2;
    int c0 = tx * 2;
    int d0 = tx * 4;

    float m[2]  = {-1e30f, -1e30f};
    float l[2]  = {0.f, 0.f};
    float accO[2][4] = {{0.f,0.f,0.f,0.f},{0.f,0.f,0.f,0.f}};

    for (int kt = 0; kt <= qb; kt++) {
        // load K/V tiles
        {
            int r  = tid >> 3;
            int dd = (tid & 7) * 8;
            const float* ksrc = k + base + (size_t)(kt * QB + r) * DD + dd;
            const float* vsrc = v + base + (size_t)(kt * QB + r) * DD + dd;
            float4 k0v = *reinterpret_cast<const float4*>(ksrc);
            float4 k1v = *reinterpret_cast<const float4*>(ksrc + 4);
            Ks[r][dd + 0] = k0v.x; Ks[r][dd + 1] = k0v.y; Ks[r][dd + 2] = k0v.z; Ks[r][dd + 3] = k0v.w;
            Ks[r][dd + 4] = k1v.x; Ks[r][dd + 5] = k1v.y; Ks[r][dd + 6] = k1v.z; Ks[r][dd + 7] = k1v.w;
            float4 v0v = *reinterpret_cast<const float4*>(vsrc);
            float4 v1v = *reinterpret_cast<const float4*>(vsrc + 4);
            *reinterpret_cast<float4*>(&Vs[r][dd])     = v0v;
            *reinterpret_cast<float4*>(&Vs[r][dd + 4]) = v1v;
        }
        __syncthreads();

        // S = Q K^T * scale  (2x2 per thread)
        float s00 = 0.f, s01 = 0.f, s10 = 0.f, s11 = 0.f;
#pragma unroll 16
        for (int dd = 0; dd < HS; dd++) {
            float q0 = Qs[r0][dd],     q1 = Qs[r0 + 1][dd];
            float kx = Ks[c0][dd],     ky = Ks[c0 + 1][dd];
            s00 += q0 * kx; s01 += q0 * ky;
            s10 += q1 * kx; s11 += q1 * ky;
        }
        const float SCALE = 0.03125f;  // D^{-1/2} = 1/32
        s00 *= SCALE; s01 *= SCALE; s10 *= SCALE; s11 *= SCALE;

        if (kt == qb) {                // causal mask on the diagonal tile
            if (c0 + 0 > r0 + 0) s00 = -1e30f;
            if (c0 + 1 > r0 + 0) s01 = -1e30f;
            if (c0 + 0 > r0 + 1) s10 = -1e30f;
            if (c0 + 1 > r0 + 1) s11 = -1e30f;
        }

        // per-row online softmax update (reduce across the 16 tx lanes)
        float rm0 = fmaxf(s00, s01);
        float rm1 = fmaxf(s10, s11);
#pragma unroll
        for (int off = 8; off; off >>= 1) {
            rm0 = fmaxf(rm0, __shfl_xor_sync(0xffffffffu, rm0, off));
            rm1 = fmaxf(rm1, __shfl_xor_sync(0xffffffffu, rm1, off));
        }
        float mn0 = fmaxf(m[0], rm0);
        float mn1 = fmaxf(m[1], rm1);
        float p00 = expf(s00 - mn0), p01 = expf(s01 - mn0);
        float p10 = expf(s10 - mn1), p11 = expf(s11 - mn1);
        float ps0 = p00 + p01, ps1 = p10 + p11;
#pragma unroll
        for (int off = 8; off; off >>= 1) {
            ps0 += __shfl_xor_sync(0xffffffffu, ps0, off);
            ps1 += __shfl_xor_sync(0xffffffffu, ps1, off);
        }
        float sc0 = expf(m[0] - mn0);
        float sc1 = expf(m[1] - mn1);
        l[0] = l[0] * sc0 + ps0;
        l[1] = l[1] * sc1 + ps1;
        m[0] = mn0; m[1] = mn1;
#pragma unroll
        for (int j = 0; j < 4; j++) { accO[0][j] *= sc0; accO[1][j] *= sc1; }

        Ps[r0][c0]         = p00;
        Ps[r0][c0 + 1]     = p01;
        Ps[r0 + 1][c0]     = p10;
        Ps[r0 + 1][c0 + 1] = p11;
        __syncthreads();

        // O += P V  (2 rows x 4 dims per thread)
#pragma unroll 8
        for (int kk = 0; kk < QB; kk++) {
            float pa = Ps[r0][kk];
            float pb = Ps[r0 + 1][kk];
            float4 vv = *reinterpret_cast<float4*>(&Vs[kk][d0]);
            accO[0][0] += pa * vv.x; accO[0][1] += pa * vv.y;
            accO[0][2] += pa * vv.z; accO[0][3] += pa * vv.w;
            accO[1][0] += pb * vv.x; accO[1][1] += pb * vv.y;
            accO[1][2] += pb * vv.z; accO[1][3] += pb * vv.w;
        }
        __syncthreads();
    }

    // final normalize + write
#pragma unroll
    for (int i = 0; i < 2; i++) {
        float invl = 1.f / l[i];
        float4 ov;
        ov.x = accO[i][0] * invl; ov.y = accO[i][1] * invl;
        ov.z = accO[i][2] * invl; ov.w = accO[i][3] * invl;
        *reinterpret_cast<float4*>(out + base + (size_t)(qb * QB + r0 + i) * DD + d0) = ov;
    }
}

// ---------------- router: logits, noisy top-2, gates, skip ----------------
__global__ __launch_bounds__(256) void router_kernel(
    const float* __restrict__ h2,
    const float* __restrict__ wr, const float* __restrict__ br,
    const float* __restrict__ wn, const float* __restrict__ bn,
    const float* __restrict__ ws, const float* __restrict__ bs,
    const float* __restrict__ noise)
{
    int t = blockIdx.x;
    int tid = threadIdx.x;
    int lane = tid & 31, warp = tid >> 5;
    __shared__ float sred[8][17];
    __shared__ float outv[17];

    const float* hr = h2 + (size_t)t * DD;
    float r[EE], nz[EE];
#pragma unroll
    for (int e = 0; e < EE; e++) { r[e] = 0.f; nz[e] = 0.f; }
    float sk = 0.f;
    for (int d = tid; d < DD; d += 256) {
        float hv = hr[d];
#pragma unroll
        for (int e = 0; e < EE; e++) {
            r[e]  += hv * wr[d * EE + e];
            nz[e] += hv * wn[d * EE + e];
        }
        sk += hv * ws[d];
    }
#pragma unroll
    for (int o = 0; o < 17; o++) {
        float val = (o < 8) ? r[o] : ((o < 16) ? nz[o - 8] : sk);
#pragma unroll
        for (int off = 16; off; off >>= 1)
            val += __shfl_xor_sync(0xffffffffu, val, off);
        if (lane == 0) sred[warp][o] = val;
    }
    __syncthreads();
    if (tid < 17) {
        float s = 0.f;
#pragma unroll
        for (int w = 0; w < 8; w++) s += sred[w][tid];
        outv[tid] = s;
    }
    __syncthreads();
    if (tid == 0) {
        float noisy[EE];
#pragma unroll
        for (int e = 0; e < EE; e++) {
            float logit = outv[e] + br[e];
            float nlin  = outv[8 + e] + bn[e];
            float sp = (nlin > 20.f) ? nlin : log1pf(expf(nlin));   // softplus
            noisy[e] = logit + noise[(size_t)t * EE + e] * sp;
        }
        int i1 = 0; float v1 = noisy[0];
#pragma unroll
        for (int e = 1; e < EE; e++) if (noisy[e] > v1) { v1 = noisy[e]; i1 = e; }
        int i2 = -1; float v2 = -1e30f;
#pragma unroll
        for (int e = 0; e < EE; e++) if (e != i1 && noisy[e] > v2) { v2 = noisy[e]; i2 = e; }
        float e2  = expf(v2 - v1);
        float inv = 1.f / (1.f + e2);
        g_idx [t * KK + 0] = i1;
        g_idx [t * KK + 1] = i2;
        g_gate[t * KK + 0] = inv;
        g_gate[t * KK + 1] = e2 * inv;
        float s = outv[16] + bs[0];
        int ns = (s > 0.f) ? 0 : 1;              // skip <=> sigmoid(s)>0.5 <=> s>0
        g_nsk[t] = ns;
        if (ns) atomicAdd(&g_n_ns, 1);
    }
}

// ---------------- per-expert dispatch (token-order scan, capacity) ----------------
__global__ __launch_bounds__(256) void dispatch_kernel()
{
    int e = blockIdx.x;
    int tid = threadIdx.x;
    __shared__ int sb[256];
    int cap = (g_n_ns * KK) / EE;
    int running = 0;
    for (int base = 0; base < NTOK; base += 256) {
        int t = base + tid;
        int f0 = g_idx[t * KK + 0];
        int f1 = g_idx[t * KK + 1];
        int mk = (g_nsk[t] && (f0 == e || f1 == e)) ? 1 : 0;
        sb[tid] = mk; __syncthreads();
        for (int off = 1; off < 256; off <<= 1) {
            int vv = (tid >= off) ? sb[tid - off] : 0;
            __syncthreads();
            sb[tid] += vv;
            __syncthreads();
        }
        if (mk) {
            int slot = running + sb[tid] - 1;
            if (slot < cap) {
                g_tok[e * CAPMAX + slot] = t;
                int j = (f0 == e) ? 0 : 1;
                g_slotmap[t * KK + j] = slot;
            }
        }
        int tot = sb[255];
        __syncthreads();
        running += tot;
    }
    if (tid == 0) g_cnt[e] = (running < cap) ? running : cap;
}

// ---------------- combine: out = x1 + (nsk ? expert mix : h2) ----------------
__global__ __launch_bounds__(256) void combine_kernel(
    const float* __restrict__ x1, const float* __restrict__ h2,
    const float* __restrict__ yout, float* __restrict__ out)
{
    int t = blockIdx.x;
    int tid = threadIdx.x;
    int d = tid * 4;
    int ns = g_nsk[t];
    float4 moe;
    if (ns) {
        int e0 = g_idx[t * KK + 0], e1 = g_idx[t * KK + 1];
        int s0 = g_slotmap[t * KK + 0], s1 = g_slotmap[t * KK + 1];
        float ga = g_gate[t * KK + 0], gb = g_gate[t * KK + 1];
        moe = make_float4(0.f, 0.f, 0.f, 0.f);
        if (s0 >= 0) {
            float4 y = *reinterpret_cast<const float4*>(yout + ((size_t)e0 * CAPMAX + s0) * DD + d);
            moe.x += ga * y.x; moe.y += ga * y.y; moe.z += ga * y.z; moe.w += ga * y.w;
        }
        if (s1 >= 0) {
            float4 y = *reinterpret_cast<const float4*>(yout + ((size_t)e1 * CAPMAX + s1) * DD + d);
            moe.x += gb * y.x; moe.y += gb * y.y; moe.z += gb * y.z; moe.w += gb * y.w;
        }
    } else {
        moe = *reinterpret_cast<const float4*>(h2 + (size_t)t * DD + d);
    }
    float4 xv = *reinterpret_cast<const float4*>(x1 + (size_t)t * DD + d);
    float4 ov;
    ov.x = xv.x + moe.x; ov.y = xv.y + moe.y;
    ov.z = xv.z + moe.z; ov.w = xv.w + moe.w;
    *reinterpret_cast<float4*>(out + (size_t)t * DD + d) = ov;
}

// ---------------- launch ----------------
extern "C" void kernel_launch(void* const* d_in, const int* in_sizes, int n_in,
                              void* d_out, int out_size)
{
    const float* x        = (const float*)d_in[0];
    const float* noise    = (const float*)d_in[1];
    const float* ln1_g    = (const float*)d_in[2];
    const float* ln1_b    = (const float*)d_in[3];
    const float* wq       = (const float*)d_in[4];
    const float* wk       = (const float*)d_in[5];
    const float* wv       = (const float*)d_in[6];
    const float* w_proj   = (const float*)d_in[7];
    const float* b_proj   = (const float*)d_in[8];
    const float* ln2_g    = (const float*)d_in[9];
    const float* ln2_b    = (const float*)d_in[10];
    const float* w_router = (const float*)d_in[11];
    const float* b_router = (const float*)d_in[12];
    const float* w_noise  = (const float*)d_in[13];
    const float* b_noise  = (const float*)d_in[14];
    const float* w_skip   = (const float*)d_in[15];
    const float* b_skip   = (const float*)d_in[16];
    const float* ew1      = (const float*)d_in[17];
    const float* eb1      = (const float*)d_in[18];
    const float* ew2      = (const float*)d_in[19];
    const float* eb2      = (const float*)d_in[20];
    float* out = (float*)d_out;

    float *p_h, *p_q, *p_k, *p_v, *p_attn, *p_x1, *p_h2, *p_mid, *p_yout;
    int *p_tok, *p_cnt;
    cudaGetSymbolAddress((void**)&p_h,    g_h);
    cudaGetSymbolAddress((void**)&p_q,    g_q);
    cudaGetSymbolAddress((void**)&p_k,    g_k);
    cudaGetSymbolAddress((void**)&p_v,    g_v);
    cudaGetSymbolAddress((void**)&p_attn, g_attn);
    cudaGetSymbolAddress((void**)&p_x1,   g_x1);
    cudaGetSymbolAddress((void**)&p_h2,   g_h2);
    cudaGetSymbolAddress((void**)&p_mid,  g_mid);
    cudaGetSymbolAddress((void**)&p_yout, g_yout);
    cudaGetSymbolAddress((void**)&p_tok,  g_tok);
    cudaGetSymbolAddress((void**)&p_cnt,  g_cnt);

    // 1. reset per-launch state
    init_kernel<<<32, 256>>>();

    // 2. LN1
    ln_kernel<<<NTOK, 256>>>(x, ln1_g, ln1_b, p_h);

    // 3. QKV projections (4096x1024x1024 each)
    gemm_k<<<dim3(8, 32, 1), 256>>>(p_h, 0, wq, 0, nullptr, 0, p_q, 0,
                                    nullptr, nullptr, 0, nullptr, NTOK, DD, DD, 0);
    gemm_k<<<dim3(8, 32, 1), 256>>>(p_h, 0, wk, 0, nullptr, 0, p_k, 0,
                                    nullptr, nullptr, 0, nullptr, NTOK, DD, DD, 0);
    gemm_k<<<dim3(8, 32, 1), 256>>>(p_h, 0, wv, 0, nullptr, 0, p_v, 0,
                                    nullptr, nullptr, 0, nullptr, NTOK, DD, DD, 0);

    // 4. flash-style causal attention
    attn_kernel<<<dim3(TT / QB, BB * HH), 256>>>(p_q, p_k, p_v, p_attn);

    // 5. output projection + bias + residual -> x1
    gemm_k<<<dim3(8, 32, 1), 256>>>(p_attn, 0, w_proj, 0, b_proj, 0, p_x1, 0,
                                    x, nullptr, 0, nullptr, NTOK, DD, DD, 0);

    // 6. LN2
    ln_kernel<<<NTOK, 256>>>(p_x1, ln2_g, ln2_b, p_h2);

    // 7. router
    router_kernel<<<NTOK, 256>>>(p_h2, w_router, b_router, w_noise, b_noise,
                                 w_skip, b_skip, noise);

    // 8. capacity-limited per-expert dispatch
    dispatch_kernel<<<EE, 256>>>();

    // 9. expert FFN layer 1 (gathered rows, +bias, ReLU): M<=1024, N=4096, K=1024
    gemm_k<<<dim3(32, 8, EE), 256>>>(p_h2, 0,
                                     ew1, (size_t)DD * DFF,
                                     eb1, (size_t)DFF,
                                     p_mid, (size_t)CAPMAX * DFF,
                                     nullptr, p_tok, CAPMAX, p_cnt,
                                     0, DD, DFF, 1);

    // 10. expert FFN layer 2 (+bias): M<=1024, N=1024, K=4096
    gemm_k<<<dim3(8, 8, EE), 256>>>(p_mid, (size_t)CAPMAX * DFF,
                                    ew2, (size_t)DFF * DD,
                                    eb2, (size_t)DD,
                                    p_yout, (size_t)CAPMAX * DD,
                                    nullptr, nullptr, 0, p_cnt,
                                    0, DFF, DD, 0);

    // 11. combine + final residual -> out
    combine_kernel<<<NTOK, 256>>>(p_x1, p_h2, p_yout, out);
}